// round 9
// baseline (speedup 1.0000x reference)
#include <cstdint>
#include <cuda_runtime.h>
#include <cuda_fp16.h>

#define NMAX 50000
#define EMAX 800000
#define PAD 136   // fp16 row pitch for smem tiles (conflict-free ldmatrix)

// ---------------- device scratch --------------------------------------------
__device__ __half g_h1[NMAX * 128];
__device__ float  g_als1[NMAX * 8];
__device__ float  g_ald1[NMAX * 8];
__device__ __half g_h2[NMAX * 16];
__device__ float  g_als2[NMAX];
__device__ float  g_ald2[NMAX];
__device__ int    g_deg[NMAX];       // in-edge count (self loop added in scan)
__device__ int    g_off[NMAX + 1];
__device__ int    g_rank[EMAX];
__device__ int    g_csr[EMAX + NMAX];
__device__ int    g_blkagg[256];
__device__ int    g_blkpre[256];
__device__ unsigned g_blkflag[256];  // 0=none, 1=aggregate ready, 2=prefix ready

// ---------------- CSR build --------------------------------------------------
__global__ void k_count(const int* __restrict__ dst, int E) {
    int i = blockIdx.x * blockDim.x + threadIdx.x;
    if (i < E) g_rank[i] = atomicAdd(&g_deg[dst[i]], 1);  // rank within dst segment
}

// single-pass scan with decoupled lookback: block-local scan + cross-block
// prefix via published aggregates. All blocks co-resident (196 << capacity).
__global__ void k_scan(int nb, int n) {
    __shared__ int sm[256];
    __shared__ int s_pre;
    int t = threadIdx.x, b = blockIdx.x;
    int i = b * 256 + t;
    int d = (i < n) ? (g_deg[i] + 1) : 0;  // +1 self loop
    sm[t] = d;
    __syncthreads();
    for (int o = 1; o < 256; o <<= 1) {
        int u = (t >= o) ? sm[t - o] : 0;
        __syncthreads();
        sm[t] += u;
        __syncthreads();
    }
    int agg = sm[255];
    if (t == 0) {
        atomicExch(&g_blkagg[b], agg);
        __threadfence();
        atomicExch(&g_blkflag[b], 1u);
        // lookback
        int pre = 0;
        for (int j = b - 1; j >= 0;) {
            unsigned f;
            do { f = atomicAdd(&g_blkflag[j], 0u); } while (f == 0u);
            if (f == 2u) { pre += atomicAdd(&g_blkpre[j], 0); break; }
            pre += atomicAdd(&g_blkagg[j], 0);
            j--;
        }
        atomicExch(&g_blkpre[b], pre + agg);
        __threadfence();
        atomicExch(&g_blkflag[b], 2u);
        s_pre = pre;
    }
    __syncthreads();
    int bpre = s_pre;
    if (b == nb - 1 && t == 255) g_off[n] = bpre + agg;
    if (i < n) {
        int off = bpre + sm[t] - d;
        g_off[i] = off;
        g_csr[off] = i;  // self loop in slot 0
    }
}

__global__ void k_scatter(const int* __restrict__ src, const int* __restrict__ dst,
                          int E) {
    int i = blockIdx.x * blockDim.x + threadIdx.x;
    if (i < E) {
        int d = dst[i];
        g_csr[g_off[d] + 1 + g_rank[i]] = src[i];  // slot 0 is the self loop
    }
}

// ---------------- GEMM1 via tensor cores (fp16 split, fp32 acc) --------------
__device__ __forceinline__ void ldsm4(unsigned a, unsigned* r) {
    asm volatile("ldmatrix.sync.aligned.m8n8.x4.shared.b16 {%0,%1,%2,%3}, [%4];"
                 : "=r"(r[0]), "=r"(r[1]), "=r"(r[2]), "=r"(r[3]) : "r"(a));
}
__device__ __forceinline__ void ldsm4t(unsigned a, unsigned* r) {
    asm volatile("ldmatrix.sync.aligned.m8n8.x4.trans.shared.b16 {%0,%1,%2,%3}, [%4];"
                 : "=r"(r[0]), "=r"(r[1]), "=r"(r[2]), "=r"(r[3]) : "r"(a));
}
__device__ __forceinline__ void mma16816(float* c, const unsigned* a, unsigned b0, unsigned b1) {
    asm volatile("mma.sync.aligned.m16n8k16.row.col.f32.f16.f16.f32 "
                 "{%0,%1,%2,%3},{%4,%5,%6,%7},{%8,%9},{%0,%1,%2,%3};"
                 : "+f"(c[0]), "+f"(c[1]), "+f"(c[2]), "+f"(c[3])
                 : "r"(a[0]), "r"(a[1]), "r"(a[2]), "r"(a[3]), "r"(b0), "r"(b1));
}

__device__ __forceinline__ void fsplit2(float f0, float f1, __half2& hi, __half2& lo) {
    hi = __floats2half2_rn(f0, f1);
    float2 h = __half22float2(hi);
    lo = __floats2half2_rn(f0 - h.x, f1 - h.y);
}

// block: 256 threads (8 warps as 4x2), C tile 128x128, K=128 in one shot.
// Epilogue also emits per-head attention logits.
__global__ void __launch_bounds__(256) k_gemm1(const float* __restrict__ x,
                                               const float* __restrict__ W,
                                               const float* __restrict__ as,
                                               const float* __restrict__ ad, int n) {
    extern __shared__ __half sh[];
    __half* Ah = sh;
    __half* Al = Ah + 128 * PAD;
    __half* Bh = Al + 128 * PAD;
    __half* Bl = Bh + 128 * PAD;
    int tid = threadIdx.x;
    int base = blockIdx.x * 128;

    const float4* xg = (const float4*)x;
    for (int i = tid; i < 4096; i += 256) {
        int r = i >> 5, c4 = i & 31;
        int gr = base + r;
        float4 v = (gr < n) ? xg[gr * 32 + c4] : make_float4(0.f, 0.f, 0.f, 0.f);
        int cc = c4 * 4;
        __half2 h, l;
        fsplit2(v.x, v.y, h, l);
        *(__half2*)&Ah[r * PAD + cc] = h;
        *(__half2*)&Al[r * PAD + cc] = l;
        fsplit2(v.z, v.w, h, l);
        *(__half2*)&Ah[r * PAD + cc + 2] = h;
        *(__half2*)&Al[r * PAD + cc + 2] = l;
    }
    const float4* wg = (const float4*)W;
    for (int i = tid; i < 4096; i += 256) {
        int r = i >> 5, c4 = i & 31;
        float4 v = wg[i];
        int cc = c4 * 4;
        __half2 h, l;
        fsplit2(v.x, v.y, h, l);
        *(__half2*)&Bh[r * PAD + cc] = h;
        *(__half2*)&Bl[r * PAD + cc] = l;
        fsplit2(v.z, v.w, h, l);
        *(__half2*)&Bh[r * PAD + cc + 2] = h;
        *(__half2*)&Bl[r * PAD + cc + 2] = l;
    }
    __syncthreads();

    int warp = tid >> 5, lane = tid & 31;
    int mw = (warp >> 1) * 32;   // 4 warps along M
    int nw = (warp & 1) * 64;    // 2 warps along N (= heads 0-3 / 4-7)
    int lr = lane & 15;
    int lk8 = (lane >> 4) * 8;

    float acc[2][8][4];
#pragma unroll
    for (int mt = 0; mt < 2; mt++)
#pragma unroll
        for (int nt = 0; nt < 8; nt++)
#pragma unroll
            for (int j = 0; j < 4; j++) acc[mt][nt][j] = 0.f;

#pragma unroll
    for (int kk = 0; kk < 8; kk++) {
        int k0 = kk * 16;
        unsigned ah[2][4], al[2][4];
#pragma unroll
        for (int mt = 0; mt < 2; mt++) {
            unsigned a = (unsigned)__cvta_generic_to_shared(
                &Ah[(mw + mt * 16 + lr) * PAD + k0 + lk8]);
            ldsm4(a, ah[mt]);
            a = (unsigned)__cvta_generic_to_shared(
                &Al[(mw + mt * 16 + lr) * PAD + k0 + lk8]);
            ldsm4(a, al[mt]);
        }
        unsigned bh[8][2], bl[8][2];
#pragma unroll
        for (int nt2 = 0; nt2 < 4; nt2++) {
            int n0 = nw + nt2 * 16;
            unsigned r4[4];
            unsigned a = (unsigned)__cvta_generic_to_shared(
                &Bh[(k0 + lr) * PAD + n0 + lk8]);
            ldsm4t(a, r4);
            bh[nt2 * 2][0] = r4[0]; bh[nt2 * 2][1] = r4[1];
            bh[nt2 * 2 + 1][0] = r4[2]; bh[nt2 * 2 + 1][1] = r4[3];
            a = (unsigned)__cvta_generic_to_shared(
                &Bl[(k0 + lr) * PAD + n0 + lk8]);
            ldsm4t(a, r4);
            bl[nt2 * 2][0] = r4[0]; bl[nt2 * 2][1] = r4[1];
            bl[nt2 * 2 + 1][0] = r4[2]; bl[nt2 * 2 + 1][1] = r4[3];
        }
#pragma unroll
        for (int mt = 0; mt < 2; mt++)
#pragma unroll
            for (int nt = 0; nt < 8; nt++) {
                mma16816(acc[mt][nt], ah[mt], bh[nt][0], bh[nt][1]);
                mma16816(acc[mt][nt], ah[mt], bl[nt][0], bl[nt][1]);
                mma16816(acc[mt][nt], al[mt], bh[nt][0], bh[nt][1]);
            }
    }

    // epilogue: store fp16 h1 + fused per-head logits
    int r0 = lane >> 2, c0l = 2 * (lane & 3);
    float asv[8][2], adv[8][2];
#pragma unroll
    for (int nt = 0; nt < 8; nt++) {
        int col = nw + nt * 8 + c0l;
        asv[nt][0] = __ldg(&as[col]);
        asv[nt][1] = __ldg(&as[col + 1]);
        adv[nt][0] = __ldg(&ad[col]);
        adv[nt][1] = __ldg(&ad[col + 1]);
    }
#pragma unroll
    for (int mt = 0; mt < 2; mt++) {
#pragma unroll
        for (int nt = 0; nt < 8; nt++) {
            int row = base + mw + mt * 16 + r0;
            int col = nw + nt * 8 + c0l;
            if (row < n)
                ((__half2*)g_h1)[(row * 128 + col) >> 1] =
                    __floats2half2_rn(acc[mt][nt][0], acc[mt][nt][1]);
            if (row + 8 < n)
                ((__half2*)g_h1)[((row + 8) * 128 + col) >> 1] =
                    __floats2half2_rn(acc[mt][nt][2], acc[mt][nt][3]);
        }
#pragma unroll
        for (int hl = 0; hl < 4; hl++) {
            int t0 = 2 * hl, t1 = 2 * hl + 1;
            float ps0 = acc[mt][t0][0] * asv[t0][0] + acc[mt][t0][1] * asv[t0][1]
                      + acc[mt][t1][0] * asv[t1][0] + acc[mt][t1][1] * asv[t1][1];
            float ps1 = acc[mt][t0][2] * asv[t0][0] + acc[mt][t0][3] * asv[t0][1]
                      + acc[mt][t1][2] * asv[t1][0] + acc[mt][t1][3] * asv[t1][1];
            float pd0 = acc[mt][t0][0] * adv[t0][0] + acc[mt][t0][1] * adv[t0][1]
                      + acc[mt][t1][0] * adv[t1][0] + acc[mt][t1][1] * adv[t1][1];
            float pd1 = acc[mt][t0][2] * adv[t0][0] + acc[mt][t0][3] * adv[t0][1]
                      + acc[mt][t1][2] * adv[t1][0] + acc[mt][t1][3] * adv[t1][1];
            ps0 += __shfl_xor_sync(0xffffffffu, ps0, 1);
            ps0 += __shfl_xor_sync(0xffffffffu, ps0, 2);
            ps1 += __shfl_xor_sync(0xffffffffu, ps1, 1);
            ps1 += __shfl_xor_sync(0xffffffffu, ps1, 2);
            pd0 += __shfl_xor_sync(0xffffffffu, pd0, 1);
            pd0 += __shfl_xor_sync(0xffffffffu, pd0, 2);
            pd1 += __shfl_xor_sync(0xffffffffu, pd1, 1);
            pd1 += __shfl_xor_sync(0xffffffffu, pd1, 2);
            if ((lane & 3) == 0) {
                int head = (nw >> 4) + hl;
                int row = base + mw + mt * 16 + r0;
                if (row < n) {
                    g_als1[row * 8 + head] = ps0;
                    g_ald1[row * 8 + head] = pd0;
                }
                if (row + 8 < n) {
                    g_als1[(row + 8) * 8 + head] = ps1;
                    g_ald1[(row + 8) * 8 + head] = pd1;
                }
            }
        }
    }
}

// ---------------- fused edge1 + GEMM2 + logits2 ------------------------------
__device__ __forceinline__ void e1acc(uint2 v, float ex, float4& acc, float& den) {
    float2 fa = __half22float2(*(__half2*)&v.x);
    float2 fb = __half22float2(*(__half2*)&v.y);
    acc.x = fmaf(ex, fa.x, acc.x);
    acc.y = fmaf(ex, fa.y, acc.y);
    acc.z = fmaf(ex, fb.x, acc.z);
    acc.w = fmaf(ex, fb.y, acc.w);
    den += ex;
}
__device__ __forceinline__ float lrelu_exp(float t) {
    t = t > 0.f ? t : 0.2f * t;
    return __expf(t);
}

// warp per dst node. 4-deep batching + capped registers for 48 warps/SM
// (the edge gather is L2-latency bound; occupancy is the binding resource).
__global__ void __launch_bounds__(256, 6) k_edge1g2(
        const float* __restrict__ b1, const float* __restrict__ W2,
        const float* __restrict__ as2v, const float* __restrict__ ad2v, int n) {
    __shared__ float Wsm[2048];       // W2 [128,16]
    __shared__ float hsm[8][128];     // per-warp hl2 row
    __shared__ float bsm[128];
    __shared__ float a2sm[16], d2sm[16];
    int tid = threadIdx.x;
    for (int i = tid; i < 2048; i += 256) Wsm[i] = W2[i];
    if (tid < 128) bsm[tid] = b1[tid];
    if (tid < 16) { a2sm[tid] = as2v[tid]; d2sm[tid] = ad2v[tid]; }
    __syncthreads();

    int warp = tid >> 5, lane = tid & 31;
    int head = lane >> 2;
    const uint2* h1v = (const uint2*)g_h1;
    int col = lane & 15;
    int kbase = (lane >> 4) * 64;

    for (int d = blockIdx.x * 8 + warp; d < n; d += gridDim.x * 8) {
        float ald = g_ald1[d * 8 + head];
        int e = g_off[d], end = g_off[d + 1];
        float4 acc = make_float4(0.f, 0.f, 0.f, 0.f);
        float den = 0.f;
        for (; e + 4 <= end; e += 4) {
            int s0 = __ldg(&g_csr[e]);
            int s1 = __ldg(&g_csr[e + 1]);
            int s2 = __ldg(&g_csr[e + 2]);
            int s3 = __ldg(&g_csr[e + 3]);
            float t0 = __ldg(&g_als1[s0 * 8 + head]) + ald;
            float t1 = __ldg(&g_als1[s1 * 8 + head]) + ald;
            float t2 = __ldg(&g_als1[s2 * 8 + head]) + ald;
            float t3 = __ldg(&g_als1[s3 * 8 + head]) + ald;
            uint2 v0 = __ldg(&h1v[s0 * 32 + lane]);
            uint2 v1 = __ldg(&h1v[s1 * 32 + lane]);
            uint2 v2 = __ldg(&h1v[s2 * 32 + lane]);
            uint2 v3 = __ldg(&h1v[s3 * 32 + lane]);
            e1acc(v0, lrelu_exp(t0), acc, den);
            e1acc(v1, lrelu_exp(t1), acc, den);
            e1acc(v2, lrelu_exp(t2), acc, den);
            e1acc(v3, lrelu_exp(t3), acc, den);
        }
        for (; e < end; e++) {
            int s = __ldg(&g_csr[e]);
            float t = __ldg(&g_als1[s * 8 + head]) + ald;
            uint2 v = __ldg(&h1v[s * 32 + lane]);
            e1acc(v, lrelu_exp(t), acc, den);
        }
        float inv = 1.f / den;
        // hl2 row (relu) into this warp's smem slice
        hsm[warp][4 * lane + 0] = fmaxf(acc.x * inv + bsm[4 * lane + 0], 0.f);
        hsm[warp][4 * lane + 1] = fmaxf(acc.y * inv + bsm[4 * lane + 1], 0.f);
        hsm[warp][4 * lane + 2] = fmaxf(acc.z * inv + bsm[4 * lane + 2], 0.f);
        hsm[warp][4 * lane + 3] = fmaxf(acc.w * inv + bsm[4 * lane + 3], 0.f);
        __syncwarp();
        // layer2 projection: lanes 0-15 k=0..63, lanes 16-31 k=64..127
        float part = 0.f;
        const float* hp = hsm[warp] + kbase;
        const float* wp = Wsm + kbase * 16 + col;
#pragma unroll 16
        for (int k = 0; k < 64; k++) part = fmaf(hp[k], wp[k * 16], part);
        part += __shfl_down_sync(0xffffffffu, part, 16);
        // lanes 0-15 now hold h2[d, col]
        float ps = part * a2sm[col], pd = part * d2sm[col];
        ps += __shfl_xor_sync(0xffffffffu, ps, 1);
        ps += __shfl_xor_sync(0xffffffffu, ps, 2);
        ps += __shfl_xor_sync(0xffffffffu, ps, 4);
        ps += __shfl_xor_sync(0xffffffffu, ps, 8);
        pd += __shfl_xor_sync(0xffffffffu, pd, 1);
        pd += __shfl_xor_sync(0xffffffffu, pd, 2);
        pd += __shfl_xor_sync(0xffffffffu, pd, 4);
        pd += __shfl_xor_sync(0xffffffffu, pd, 8);
        if (lane < 16) g_h2[d * 16 + col] = __float2half_rn(part);
        if (lane == 0) { g_als2[d] = ps; g_ald2[d] = pd; }
        __syncwarp();
    }
}

// ---------------- edge pass layer2: 16 lanes per dst node, 4-deep ------------
__global__ void __launch_bounds__(256, 6) k_edge2(
        const float* __restrict__ b2, float* __restrict__ out, int n) {
    int gid = blockIdx.x * blockDim.x + threadIdx.x;
    int node = gid >> 4, lane = gid & 15;
    if (node >= n) return;
    float ald = g_ald2[node];
    int e = g_off[node], end = g_off[node + 1];
    float acc = 0.f, den = 0.f;
    for (; e + 4 <= end; e += 4) {
        int s0 = __ldg(&g_csr[e]);
        int s1 = __ldg(&g_csr[e + 1]);
        int s2 = __ldg(&g_csr[e + 2]);
        int s3 = __ldg(&g_csr[e + 3]);
        float t0 = __ldg(&g_als2[s0]) + ald;
        float t1 = __ldg(&g_als2[s1]) + ald;
        float t2 = __ldg(&g_als2[s2]) + ald;
        float t3 = __ldg(&g_als2[s3]) + ald;
        float h0 = __half2float(g_h2[s0 * 16 + lane]);
        float h1 = __half2float(g_h2[s1 * 16 + lane]);
        float h2 = __half2float(g_h2[s2 * 16 + lane]);
        float h3 = __half2float(g_h2[s3 * 16 + lane]);
        float e0 = lrelu_exp(t0), e1 = lrelu_exp(t1);
        float e2 = lrelu_exp(t2), e3 = lrelu_exp(t3);
        acc = fmaf(e0, h0, acc); den += e0;
        acc = fmaf(e1, h1, acc); den += e1;
        acc = fmaf(e2, h2, acc); den += e2;
        acc = fmaf(e3, h3, acc); den += e3;
    }
    for (; e < end; e++) {
        int s = __ldg(&g_csr[e]);
        float t = __ldg(&g_als2[s]) + ald;
        float ex = lrelu_exp(t);
        acc = fmaf(ex, __half2float(g_h2[s * 16 + lane]), acc);
        den += ex;
    }
    out[node * 16 + lane] = fmaxf(acc / den + b2[lane], 0.f);
}

// ---------------- launch -----------------------------------------------------
extern "C" void kernel_launch(void* const* d_in, const int* in_sizes, int n_in,
                              void* d_out, int out_size) {
    const float* x     = (const float*)d_in[0];
    const int*   ei    = (const int*)d_in[1];
    const float* W1    = (const float*)d_in[2];
    const float* asrc1 = (const float*)d_in[3];
    const float* adst1 = (const float*)d_in[4];
    const float* b1    = (const float*)d_in[5];
    const float* W2    = (const float*)d_in[6];
    const float* asrc2 = (const float*)d_in[7];
    const float* adst2 = (const float*)d_in[8];
    const float* b2    = (const float*)d_in[9];

    int n = in_sizes[0] / 128;
    int E = in_sizes[1] / 2;
    const int* src = ei;
    const int* dst = ei + E;
    int nb = (n + 255) / 256;

    // fork a side stream: CSR build runs concurrently with GEMM1
    cudaStream_t s2;
    cudaStreamCreateWithFlags(&s2, cudaStreamNonBlocking);
    cudaEvent_t evFork, evJoin;
    cudaEventCreateWithFlags(&evFork, cudaEventDisableTiming);
    cudaEventCreateWithFlags(&evJoin, cudaEventDisableTiming);

    cudaEventRecord(evFork, 0);
    cudaStreamWaitEvent(s2, evFork, 0);

    // CSR build chain on s2
    void* degp = nullptr;
    void* flagp = nullptr;
    cudaGetSymbolAddress(&degp, g_deg);
    cudaGetSymbolAddress(&flagp, g_blkflag);
    cudaMemsetAsync(degp, 0, NMAX * sizeof(int), s2);
    cudaMemsetAsync(flagp, 0, 256 * sizeof(unsigned), s2);
    k_count<<<(E + 255) / 256, 256, 0, s2>>>(dst, E);
    k_scan<<<nb, 256, 0, s2>>>(nb, n);
    k_scatter<<<(E + 255) / 256, 256, 0, s2>>>(src, dst, E);
    cudaEventRecord(evJoin, s2);

    // GEMM1 (with fused logits) on the main stream, concurrent with CSR build
    const int SMEM1 = 4 * 128 * PAD * (int)sizeof(__half);  // 139264
    cudaFuncSetAttribute(k_gemm1, cudaFuncAttributeMaxDynamicSharedMemorySize, SMEM1);
    k_gemm1<<<(n + 127) / 128, 256, SMEM1>>>(x, W1, asrc1, adst1, n);

    // join: fused edge1+gemm2 needs both CSR and gemm1
    cudaStreamWaitEvent((cudaStream_t)0, evJoin, 0);
    k_edge1g2<<<(n + 7) / 8, 256>>>(b1, W2, asrc2, adst2, n);

    // layer 2 attention
    k_edge2<<<(n * 16 + 255) / 256, 256>>>(b2, (float*)d_out, n);

    cudaEventDestroy(evFork);
    cudaEventDestroy(evJoin);
    cudaStreamDestroy(s2);
}

// round 10
// speedup vs baseline: 1.1506x; 1.1506x over previous
#include <cstdint>
#include <cuda_runtime.h>
#include <cuda_fp16.h>

#define NMAX 50000
#define EMAX 800000
#define PAD 136   // fp16 row pitch for smem tiles (conflict-free ldmatrix)

// ---------------- device scratch --------------------------------------------
__device__ __half g_h1[NMAX * 128];
__device__ float  g_als1[NMAX * 8];
__device__ float  g_ald1[NMAX * 8];
__device__ __half g_h2[NMAX * 16];
__device__ float  g_als2[NMAX];
__device__ float  g_ald2[NMAX];
__device__ int    g_deg[NMAX];       // in-edge count (self loop added in scan)
__device__ int    g_off[NMAX + 1];
__device__ int    g_rank[EMAX];
__device__ int    g_csr[EMAX + NMAX];
__device__ int    g_bsum[256];

// ---------------- CSR build --------------------------------------------------
__global__ void k_count(const int* __restrict__ dst, int E) {
    int i = blockIdx.x * blockDim.x + threadIdx.x;
    if (i < E) g_rank[i] = atomicAdd(&g_deg[dst[i]], 1);  // rank within dst segment
}

__global__ void k_bsum(int n) {
    __shared__ int sm[256];
    int t = threadIdx.x;
    int i = blockIdx.x * 256 + t;
    sm[t] = (i < n) ? (g_deg[i] + 1) : 0;  // +1 self loop
    __syncthreads();
    for (int o = 128; o > 0; o >>= 1) {
        if (t < o) sm[t] += sm[t + o];
        __syncthreads();
    }
    if (t == 0) g_bsum[blockIdx.x] = sm[0];
}

// every block scans the (<=256) block sums locally, then scans its own
// 256 degrees and writes offsets + self-loop slot.
__global__ void k_offsets(int nb, int n) {
    __shared__ int sb[256];
    __shared__ int sm[256];
    int t = threadIdx.x;
    sb[t] = (t < nb) ? g_bsum[t] : 0;
    __syncthreads();
    for (int o = 1; o < 256; o <<= 1) {
        int u = (t >= o) ? sb[t - o] : 0;
        __syncthreads();
        sb[t] += u;
        __syncthreads();
    }
    int bpre = (blockIdx.x == 0) ? 0 : sb[blockIdx.x - 1];
    if (blockIdx.x == 0 && t == 255) g_off[n] = sb[255];
    int i = blockIdx.x * 256 + t;
    int d = (i < n) ? (g_deg[i] + 1) : 0;
    sm[t] = d;
    __syncthreads();
    for (int o = 1; o < 256; o <<= 1) {
        int u = (t >= o) ? sm[t - o] : 0;
        __syncthreads();
        sm[t] += u;
        __syncthreads();
    }
    if (i < n) {
        int off = bpre + sm[t] - d;
        g_off[i] = off;
        g_csr[off] = i;  // self loop in slot 0
    }
}

__global__ void k_scatter(const int* __restrict__ src, const int* __restrict__ dst,
                          int E) {
    int i = blockIdx.x * blockDim.x + threadIdx.x;
    if (i < E) {
        int d = dst[i];
        g_csr[g_off[d] + 1 + g_rank[i]] = src[i];  // slot 0 is the self loop
    }
}

// ---------------- GEMM1 via tensor cores (2-term fp16 split, fp32 acc) -------
__device__ __forceinline__ void ldsm4(unsigned a, unsigned* r) {
    asm volatile("ldmatrix.sync.aligned.m8n8.x4.shared.b16 {%0,%1,%2,%3}, [%4];"
                 : "=r"(r[0]), "=r"(r[1]), "=r"(r[2]), "=r"(r[3]) : "r"(a));
}
__device__ __forceinline__ void ldsm4t(unsigned a, unsigned* r) {
    asm volatile("ldmatrix.sync.aligned.m8n8.x4.trans.shared.b16 {%0,%1,%2,%3}, [%4];"
                 : "=r"(r[0]), "=r"(r[1]), "=r"(r[2]), "=r"(r[3]) : "r"(a));
}
__device__ __forceinline__ void mma16816(float* c, const unsigned* a, unsigned b0, unsigned b1) {
    asm volatile("mma.sync.aligned.m16n8k16.row.col.f32.f16.f16.f32 "
                 "{%0,%1,%2,%3},{%4,%5,%6,%7},{%8,%9},{%0,%1,%2,%3};"
                 : "+f"(c[0]), "+f"(c[1]), "+f"(c[2]), "+f"(c[3])
                 : "r"(a[0]), "r"(a[1]), "r"(a[2]), "r"(a[3]), "r"(b0), "r"(b1));
}

__device__ __forceinline__ void fsplit2(float f0, float f1, __half2& hi, __half2& lo) {
    hi = __floats2half2_rn(f0, f1);
    float2 h = __half22float2(hi);
    lo = __floats2half2_rn(f0 - h.x, f1 - h.y);
}

// block: 256 threads (8 warps as 4x2), C tile 128x128, K=128 in one shot.
// x stored plain fp16 (Ah); W split hi/lo (Bh, Bl): acc = Ah*Bh + Ah*Bl.
// 102 KB smem -> 2 blocks/SM (occupancy was the binding resource at 139 KB).
// Epilogue also emits per-head attention logits.
__global__ void __launch_bounds__(256) k_gemm1(const float* __restrict__ x,
                                               const float* __restrict__ W,
                                               const float* __restrict__ as,
                                               const float* __restrict__ ad, int n) {
    extern __shared__ __half sh[];
    __half* Ah = sh;
    __half* Bh = Ah + 128 * PAD;
    __half* Bl = Bh + 128 * PAD;
    int tid = threadIdx.x;
    int base = blockIdx.x * 128;

    const float4* xg = (const float4*)x;
    for (int i = tid; i < 4096; i += 256) {
        int r = i >> 5, c4 = i & 31;
        int gr = base + r;
        float4 v = (gr < n) ? xg[gr * 32 + c4] : make_float4(0.f, 0.f, 0.f, 0.f);
        int cc = c4 * 4;
        *(__half2*)&Ah[r * PAD + cc] = __floats2half2_rn(v.x, v.y);
        *(__half2*)&Ah[r * PAD + cc + 2] = __floats2half2_rn(v.z, v.w);
    }
    const float4* wg = (const float4*)W;
    for (int i = tid; i < 4096; i += 256) {
        int r = i >> 5, c4 = i & 31;
        float4 v = wg[i];
        int cc = c4 * 4;
        __half2 h, l;
        fsplit2(v.x, v.y, h, l);
        *(__half2*)&Bh[r * PAD + cc] = h;
        *(__half2*)&Bl[r * PAD + cc] = l;
        fsplit2(v.z, v.w, h, l);
        *(__half2*)&Bh[r * PAD + cc + 2] = h;
        *(__half2*)&Bl[r * PAD + cc + 2] = l;
    }
    __syncthreads();

    int warp = tid >> 5, lane = tid & 31;
    int mw = (warp >> 1) * 32;   // 4 warps along M
    int nw = (warp & 1) * 64;    // 2 warps along N (= heads 0-3 / 4-7)
    int lr = lane & 15;
    int lk8 = (lane >> 4) * 8;

    float acc[2][8][4];
#pragma unroll
    for (int mt = 0; mt < 2; mt++)
#pragma unroll
        for (int nt = 0; nt < 8; nt++)
#pragma unroll
            for (int j = 0; j < 4; j++) acc[mt][nt][j] = 0.f;

#pragma unroll
    for (int kk = 0; kk < 8; kk++) {
        int k0 = kk * 16;
        unsigned ah[2][4];
#pragma unroll
        for (int mt = 0; mt < 2; mt++) {
            unsigned a = (unsigned)__cvta_generic_to_shared(
                &Ah[(mw + mt * 16 + lr) * PAD + k0 + lk8]);
            ldsm4(a, ah[mt]);
        }
        unsigned bh[8][2], bl[8][2];
#pragma unroll
        for (int nt2 = 0; nt2 < 4; nt2++) {
            int n0 = nw + nt2 * 16;
            unsigned r4[4];
            unsigned a = (unsigned)__cvta_generic_to_shared(
                &Bh[(k0 + lr) * PAD + n0 + lk8]);
            ldsm4t(a, r4);
            bh[nt2 * 2][0] = r4[0]; bh[nt2 * 2][1] = r4[1];
            bh[nt2 * 2 + 1][0] = r4[2]; bh[nt2 * 2 + 1][1] = r4[3];
            a = (unsigned)__cvta_generic_to_shared(
                &Bl[(k0 + lr) * PAD + n0 + lk8]);
            ldsm4t(a, r4);
            bl[nt2 * 2][0] = r4[0]; bl[nt2 * 2][1] = r4[1];
            bl[nt2 * 2 + 1][0] = r4[2]; bl[nt2 * 2 + 1][1] = r4[3];
        }
#pragma unroll
        for (int mt = 0; mt < 2; mt++)
#pragma unroll
            for (int nt = 0; nt < 8; nt++) {
                mma16816(acc[mt][nt], ah[mt], bh[nt][0], bh[nt][1]);
                mma16816(acc[mt][nt], ah[mt], bl[nt][0], bl[nt][1]);
            }
    }

    // epilogue: store fp16 h1 + fused per-head logits
    int r0 = lane >> 2, c0l = 2 * (lane & 3);
    float asv[8][2], adv[8][2];
#pragma unroll
    for (int nt = 0; nt < 8; nt++) {
        int col = nw + nt * 8 + c0l;
        asv[nt][0] = __ldg(&as[col]);
        asv[nt][1] = __ldg(&as[col + 1]);
        adv[nt][0] = __ldg(&ad[col]);
        adv[nt][1] = __ldg(&ad[col + 1]);
    }
#pragma unroll
    for (int mt = 0; mt < 2; mt++) {
#pragma unroll
        for (int nt = 0; nt < 8; nt++) {
            int row = base + mw + mt * 16 + r0;
            int col = nw + nt * 8 + c0l;
            if (row < n)
                ((__half2*)g_h1)[(row * 128 + col) >> 1] =
                    __floats2half2_rn(acc[mt][nt][0], acc[mt][nt][1]);
            if (row + 8 < n)
                ((__half2*)g_h1)[((row + 8) * 128 + col) >> 1] =
                    __floats2half2_rn(acc[mt][nt][2], acc[mt][nt][3]);
        }
#pragma unroll
        for (int hl = 0; hl < 4; hl++) {
            int t0 = 2 * hl, t1 = 2 * hl + 1;
            float ps0 = acc[mt][t0][0] * asv[t0][0] + acc[mt][t0][1] * asv[t0][1]
                      + acc[mt][t1][0] * asv[t1][0] + acc[mt][t1][1] * asv[t1][1];
            float ps1 = acc[mt][t0][2] * asv[t0][0] + acc[mt][t0][3] * asv[t0][1]
                      + acc[mt][t1][2] * asv[t1][0] + acc[mt][t1][3] * asv[t1][1];
            float pd0 = acc[mt][t0][0] * adv[t0][0] + acc[mt][t0][1] * adv[t0][1]
                      + acc[mt][t1][0] * adv[t1][0] + acc[mt][t1][1] * adv[t1][1];
            float pd1 = acc[mt][t0][2] * adv[t0][0] + acc[mt][t0][3] * adv[t0][1]
                      + acc[mt][t1][2] * adv[t1][0] + acc[mt][t1][3] * adv[t1][1];
            ps0 += __shfl_xor_sync(0xffffffffu, ps0, 1);
            ps0 += __shfl_xor_sync(0xffffffffu, ps0, 2);
            ps1 += __shfl_xor_sync(0xffffffffu, ps1, 1);
            ps1 += __shfl_xor_sync(0xffffffffu, ps1, 2);
            pd0 += __shfl_xor_sync(0xffffffffu, pd0, 1);
            pd0 += __shfl_xor_sync(0xffffffffu, pd0, 2);
            pd1 += __shfl_xor_sync(0xffffffffu, pd1, 1);
            pd1 += __shfl_xor_sync(0xffffffffu, pd1, 2);
            if ((lane & 3) == 0) {
                int head = (nw >> 4) + hl;
                int row = base + mw + mt * 16 + r0;
                if (row < n) {
                    g_als1[row * 8 + head] = ps0;
                    g_ald1[row * 8 + head] = pd0;
                }
                if (row + 8 < n) {
                    g_als1[(row + 8) * 8 + head] = ps1;
                    g_ald1[(row + 8) * 8 + head] = pd1;
                }
            }
        }
    }
}

// ---------------- fused edge1 + GEMM2 + logits2 ------------------------------
__device__ __forceinline__ void e1acc(uint2 v, float ex, float4& acc, float& den) {
    float2 fa = __half22float2(*(__half2*)&v.x);
    float2 fb = __half22float2(*(__half2*)&v.y);
    acc.x = fmaf(ex, fa.x, acc.x);
    acc.y = fmaf(ex, fa.y, acc.y);
    acc.z = fmaf(ex, fb.x, acc.z);
    acc.w = fmaf(ex, fb.y, acc.w);
    den += ex;
}
__device__ __forceinline__ float lrelu_exp(float t) {
    t = t > 0.f ? t : 0.2f * t;
    return __expf(t);
}

// warp per dst node (one node per warp at launch; grid-stride as a guard).
// After softmax-aggregate, the same warp does the [1x128]x[128x16] layer-2
// projection from smem + layer-2 logits.
__global__ void __launch_bounds__(256) k_edge1g2(
        const float* __restrict__ b1, const float* __restrict__ W2,
        const float* __restrict__ as2v, const float* __restrict__ ad2v, int n) {
    __shared__ float Wsm[2048];       // W2 [128,16]
    __shared__ float hsm[8][128];     // per-warp hl2 row
    __shared__ float bsm[128];
    __shared__ float a2sm[16], d2sm[16];
    int tid = threadIdx.x;
    for (int i = tid; i < 2048; i += 256) Wsm[i] = W2[i];
    if (tid < 128) bsm[tid] = b1[tid];
    if (tid < 16) { a2sm[tid] = as2v[tid]; d2sm[tid] = ad2v[tid]; }
    __syncthreads();

    int warp = tid >> 5, lane = tid & 31;
    int head = lane >> 2;
    const uint2* h1v = (const uint2*)g_h1;
    int col = lane & 15;
    int kbase = (lane >> 4) * 64;
    float a2c = a2sm[col], d2c = d2sm[col];
    float b0 = bsm[4 * lane], b1v = bsm[4 * lane + 1],
          b2v = bsm[4 * lane + 2], b3v = bsm[4 * lane + 3];

    for (int d = blockIdx.x * 8 + warp; d < n; d += gridDim.x * 8) {
        float ald = g_ald1[d * 8 + head];
        int e = g_off[d], end = g_off[d + 1];
        float4 acc = make_float4(0.f, 0.f, 0.f, 0.f);
        float den = 0.f;
        for (; e + 8 <= end; e += 8) {
            int s[8];
            float t[8];
            uint2 v[8];
#pragma unroll
            for (int j = 0; j < 8; j++) s[j] = __ldg(&g_csr[e + j]);
#pragma unroll
            for (int j = 0; j < 8; j++) t[j] = __ldg(&g_als1[s[j] * 8 + head]) + ald;
#pragma unroll
            for (int j = 0; j < 8; j++) v[j] = __ldg(&h1v[s[j] * 32 + lane]);
#pragma unroll
            for (int j = 0; j < 8; j++) e1acc(v[j], lrelu_exp(t[j]), acc, den);
        }
        for (; e + 4 <= end; e += 4) {
            int s0 = __ldg(&g_csr[e]);
            int s1 = __ldg(&g_csr[e + 1]);
            int s2 = __ldg(&g_csr[e + 2]);
            int s3 = __ldg(&g_csr[e + 3]);
            float t0 = __ldg(&g_als1[s0 * 8 + head]) + ald;
            float t1 = __ldg(&g_als1[s1 * 8 + head]) + ald;
            float t2 = __ldg(&g_als1[s2 * 8 + head]) + ald;
            float t3 = __ldg(&g_als1[s3 * 8 + head]) + ald;
            uint2 v0 = __ldg(&h1v[s0 * 32 + lane]);
            uint2 v1 = __ldg(&h1v[s1 * 32 + lane]);
            uint2 v2 = __ldg(&h1v[s2 * 32 + lane]);
            uint2 v3 = __ldg(&h1v[s3 * 32 + lane]);
            e1acc(v0, lrelu_exp(t0), acc, den);
            e1acc(v1, lrelu_exp(t1), acc, den);
            e1acc(v2, lrelu_exp(t2), acc, den);
            e1acc(v3, lrelu_exp(t3), acc, den);
        }
        for (; e < end; e++) {
            int s = __ldg(&g_csr[e]);
            float t = __ldg(&g_als1[s * 8 + head]) + ald;
            uint2 v = __ldg(&h1v[s * 32 + lane]);
            e1acc(v, lrelu_exp(t), acc, den);
        }
        float inv = 1.f / den;
        // hl2 row (relu) into this warp's smem slice
        hsm[warp][4 * lane + 0] = fmaxf(acc.x * inv + b0, 0.f);
        hsm[warp][4 * lane + 1] = fmaxf(acc.y * inv + b1v, 0.f);
        hsm[warp][4 * lane + 2] = fmaxf(acc.z * inv + b2v, 0.f);
        hsm[warp][4 * lane + 3] = fmaxf(acc.w * inv + b3v, 0.f);
        __syncwarp();
        // layer2 projection: lanes 0-15 k=0..63, lanes 16-31 k=64..127
        float part = 0.f;
        const float* hp = hsm[warp] + kbase;
        const float* wp = Wsm + kbase * 16 + col;
#pragma unroll 16
        for (int k = 0; k < 64; k++) part = fmaf(hp[k], wp[k * 16], part);
        part += __shfl_down_sync(0xffffffffu, part, 16);
        // lanes 0-15 now hold h2[d, col]
        float ps = part * a2c, pd = part * d2c;
        ps += __shfl_xor_sync(0xffffffffu, ps, 1);
        ps += __shfl_xor_sync(0xffffffffu, ps, 2);
        ps += __shfl_xor_sync(0xffffffffu, ps, 4);
        ps += __shfl_xor_sync(0xffffffffu, ps, 8);
        pd += __shfl_xor_sync(0xffffffffu, pd, 1);
        pd += __shfl_xor_sync(0xffffffffu, pd, 2);
        pd += __shfl_xor_sync(0xffffffffu, pd, 4);
        pd += __shfl_xor_sync(0xffffffffu, pd, 8);
        if (lane < 16) g_h2[d * 16 + col] = __float2half_rn(part);
        if (lane == 0) { g_als2[d] = ps; g_ald2[d] = pd; }
        __syncwarp();
    }
}

// ---------------- edge pass layer2: 16 lanes per dst node, 8-deep ------------
__global__ void k_edge2(const float* __restrict__ b2, float* __restrict__ out, int n) {
    int gid = blockIdx.x * blockDim.x + threadIdx.x;
    int node = gid >> 4, lane = gid & 15;
    if (node >= n) return;
    float ald = g_ald2[node];
    int e = g_off[node], end = g_off[node + 1];
    float acc = 0.f, den = 0.f;
    for (; e + 8 <= end; e += 8) {
        int s[8];
        float t[8], h[8];
#pragma unroll
        for (int j = 0; j < 8; j++) s[j] = __ldg(&g_csr[e + j]);
#pragma unroll
        for (int j = 0; j < 8; j++) t[j] = __ldg(&g_als2[s[j]]) + ald;
#pragma unroll
        for (int j = 0; j < 8; j++) h[j] = __half2float(g_h2[s[j] * 16 + lane]);
#pragma unroll
        for (int j = 0; j < 8; j++) {
            float ex = lrelu_exp(t[j]);
            acc = fmaf(ex, h[j], acc);
            den += ex;
        }
    }
    for (; e < end; e++) {
        int s = __ldg(&g_csr[e]);
        float t = __ldg(&g_als2[s]) + ald;
        float ex = lrelu_exp(t);
        acc = fmaf(ex, __half2float(g_h2[s * 16 + lane]), acc);
        den += ex;
    }
    out[node * 16 + lane] = fmaxf(acc / den + b2[lane], 0.f);
}

// ---------------- launch -----------------------------------------------------
extern "C" void kernel_launch(void* const* d_in, const int* in_sizes, int n_in,
                              void* d_out, int out_size) {
    const float* x     = (const float*)d_in[0];
    const int*   ei    = (const int*)d_in[1];
    const float* W1    = (const float*)d_in[2];
    const float* asrc1 = (const float*)d_in[3];
    const float* adst1 = (const float*)d_in[4];
    const float* b1    = (const float*)d_in[5];
    const float* W2    = (const float*)d_in[6];
    const float* asrc2 = (const float*)d_in[7];
    const float* adst2 = (const float*)d_in[8];
    const float* b2    = (const float*)d_in[9];

    int n = in_sizes[0] / 128;
    int E = in_sizes[1] / 2;
    const int* src = ei;
    const int* dst = ei + E;
    int nb = (n + 255) / 256;

    // fork a side stream: CSR build runs concurrently with GEMM1
    cudaStream_t s2;
    cudaStreamCreateWithFlags(&s2, cudaStreamNonBlocking);
    cudaEvent_t evFork, evJoin;
    cudaEventCreateWithFlags(&evFork, cudaEventDisableTiming);
    cudaEventCreateWithFlags(&evJoin, cudaEventDisableTiming);

    cudaEventRecord(evFork, 0);
    cudaStreamWaitEvent(s2, evFork, 0);

    // CSR build chain on s2
    void* degp = nullptr;
    cudaGetSymbolAddress(&degp, g_deg);
    cudaMemsetAsync(degp, 0, NMAX * sizeof(int), s2);
    k_count<<<(E + 255) / 256, 256, 0, s2>>>(dst, E);
    k_bsum<<<nb, 256, 0, s2>>>(n);
    k_offsets<<<nb, 256, 0, s2>>>(nb, n);
    k_scatter<<<(E + 255) / 256, 256, 0, s2>>>(src, dst, E);
    cudaEventRecord(evJoin, s2);

    // GEMM1 (with fused logits) on the main stream, concurrent with CSR build
    const int SMEM1 = 3 * 128 * PAD * (int)sizeof(__half);  // 104448 -> 2 blocks/SM
    cudaFuncSetAttribute(k_gemm1, cudaFuncAttributeMaxDynamicSharedMemorySize, SMEM1);
    k_gemm1<<<(n + 127) / 128, 256, SMEM1>>>(x, W1, asrc1, adst1, n);

    // join: fused edge1+gemm2 needs both CSR and gemm1
    cudaStreamWaitEvent((cudaStream_t)0, evJoin, 0);
    k_edge1g2<<<(n + 7) / 8, 256>>>(b1, W2, asrc2, adst2, n);

    // layer 2 attention
    k_edge2<<<(n * 16 + 255) / 256, 256>>>(b2, (float*)d_out, n);

    cudaEventDestroy(evFork);
    cudaEventDestroy(evJoin);
    cudaStreamDestroy(s2);
}

// round 11
// speedup vs baseline: 1.2296x; 1.0687x over previous
#include <cstdint>
#include <cuda_runtime.h>
#include <cuda_fp16.h>

#define NMAX 50000
#define EMAX 800000
#define PAD 136   // fp16 row pitch for smem tiles (conflict-free ldmatrix)

// ---------------- device scratch --------------------------------------------
__device__ __half g_h1[NMAX * 128];
__device__ float  g_als1[NMAX * 8];
__device__ float  g_ald1[NMAX * 8];
__device__ __half g_h2[NMAX * 16];
__device__ float  g_als2[NMAX];
__device__ float  g_ald2[NMAX];
__device__ int    g_deg[NMAX];       // in-edge count (self loop added at alloc)
__device__ int    g_off[NMAX];       // start of each node's csr segment
__device__ int    g_rank[EMAX];
__device__ int    g_csr[EMAX + NMAX];
__device__ int    g_ctr;             // bump allocator for csr segments

// ---------------- CSR build --------------------------------------------------
__global__ void k_count(const int* __restrict__ dst, int E) {
    int i = blockIdx.x * blockDim.x + threadIdx.x;
    if (i < E) g_rank[i] = atomicAdd(&g_deg[dst[i]], 1);  // rank within dst segment
}

// segment allocation: block-local scan + ONE atomicAdd per block on a global
// counter. Segments need not be ordered by node id (aggregation commutes),
// which removes the scan chain (bsum+offsets) entirely.
__global__ void k_alloc(int n) {
    __shared__ int sm[256];
    __shared__ int sbase;
    int t = threadIdx.x;
    int i = blockIdx.x * 256 + t;
    int d = (i < n) ? (g_deg[i] + 1) : 0;  // +1 self loop
    sm[t] = d;
    __syncthreads();
    for (int o = 1; o < 256; o <<= 1) {
        int u = (t >= o) ? sm[t - o] : 0;
        __syncthreads();
        sm[t] += u;
        __syncthreads();
    }
    if (t == 255) sbase = atomicAdd(&g_ctr, sm[255]);
    __syncthreads();
    if (i < n) {
        int off = sbase + sm[t] - d;
        g_off[i] = off;
        g_csr[off] = i;  // self loop in slot 0
    }
}

__global__ void k_scatter(const int* __restrict__ src, const int* __restrict__ dst,
                          int E) {
    int i = blockIdx.x * blockDim.x + threadIdx.x;
    if (i < E) {
        int d = dst[i];
        g_csr[g_off[d] + 1 + g_rank[i]] = src[i];  // slot 0 is the self loop
    }
}

// ---------------- GEMM1 via tensor cores (plain fp16, fp32 acc) --------------
__device__ __forceinline__ void ldsm4(unsigned a, unsigned* r) {
    asm volatile("ldmatrix.sync.aligned.m8n8.x4.shared.b16 {%0,%1,%2,%3}, [%4];"
                 : "=r"(r[0]), "=r"(r[1]), "=r"(r[2]), "=r"(r[3]) : "r"(a));
}
__device__ __forceinline__ void ldsm4t(unsigned a, unsigned* r) {
    asm volatile("ldmatrix.sync.aligned.m8n8.x4.trans.shared.b16 {%0,%1,%2,%3}, [%4];"
                 : "=r"(r[0]), "=r"(r[1]), "=r"(r[2]), "=r"(r[3]) : "r"(a));
}
__device__ __forceinline__ void mma16816(float* c, const unsigned* a, unsigned b0, unsigned b1) {
    asm volatile("mma.sync.aligned.m16n8k16.row.col.f32.f16.f16.f32 "
                 "{%0,%1,%2,%3},{%4,%5,%6,%7},{%8,%9},{%0,%1,%2,%3};"
                 : "+f"(c[0]), "+f"(c[1]), "+f"(c[2]), "+f"(c[3])
                 : "r"(a[0]), "r"(a[1]), "r"(a[2]), "r"(a[3]), "r"(b0), "r"(b1));
}

// block: 256 threads (8 warps as 4x2), C tile 128x128, K=128 in one shot.
// x and W both plain fp16; 68 KB smem -> 3 blocks/SM.
// Epilogue also emits per-head attention logits.
__global__ void __launch_bounds__(256) k_gemm1(const float* __restrict__ x,
                                               const float* __restrict__ W,
                                               const float* __restrict__ as,
                                               const float* __restrict__ ad, int n) {
    extern __shared__ __half sh[];
    __half* Ah = sh;
    __half* Bh = Ah + 128 * PAD;
    int tid = threadIdx.x;
    int base = blockIdx.x * 128;

    const float4* xg = (const float4*)x;
    for (int i = tid; i < 4096; i += 256) {
        int r = i >> 5, c4 = i & 31;
        int gr = base + r;
        float4 v = (gr < n) ? xg[gr * 32 + c4] : make_float4(0.f, 0.f, 0.f, 0.f);
        int cc = c4 * 4;
        *(__half2*)&Ah[r * PAD + cc] = __floats2half2_rn(v.x, v.y);
        *(__half2*)&Ah[r * PAD + cc + 2] = __floats2half2_rn(v.z, v.w);
    }
    const float4* wg = (const float4*)W;
    for (int i = tid; i < 4096; i += 256) {
        int r = i >> 5, c4 = i & 31;
        float4 v = wg[i];
        int cc = c4 * 4;
        *(__half2*)&Bh[r * PAD + cc] = __floats2half2_rn(v.x, v.y);
        *(__half2*)&Bh[r * PAD + cc + 2] = __floats2half2_rn(v.z, v.w);
    }
    __syncthreads();

    int warp = tid >> 5, lane = tid & 31;
    int mw = (warp >> 1) * 32;   // 4 warps along M
    int nw = (warp & 1) * 64;    // 2 warps along N (= heads 0-3 / 4-7)
    int lr = lane & 15;
    int lk8 = (lane >> 4) * 8;

    float acc[2][8][4];
#pragma unroll
    for (int mt = 0; mt < 2; mt++)
#pragma unroll
        for (int nt = 0; nt < 8; nt++)
#pragma unroll
            for (int j = 0; j < 4; j++) acc[mt][nt][j] = 0.f;

#pragma unroll
    for (int kk = 0; kk < 8; kk++) {
        int k0 = kk * 16;
        unsigned ah[2][4];
#pragma unroll
        for (int mt = 0; mt < 2; mt++) {
            unsigned a = (unsigned)__cvta_generic_to_shared(
                &Ah[(mw + mt * 16 + lr) * PAD + k0 + lk8]);
            ldsm4(a, ah[mt]);
        }
        unsigned bh[8][2];
#pragma unroll
        for (int nt2 = 0; nt2 < 4; nt2++) {
            int n0 = nw + nt2 * 16;
            unsigned r4[4];
            unsigned a = (unsigned)__cvta_generic_to_shared(
                &Bh[(k0 + lr) * PAD + n0 + lk8]);
            ldsm4t(a, r4);
            bh[nt2 * 2][0] = r4[0]; bh[nt2 * 2][1] = r4[1];
            bh[nt2 * 2 + 1][0] = r4[2]; bh[nt2 * 2 + 1][1] = r4[3];
        }
#pragma unroll
        for (int mt = 0; mt < 2; mt++)
#pragma unroll
            for (int nt = 0; nt < 8; nt++)
                mma16816(acc[mt][nt], ah[mt], bh[nt][0], bh[nt][1]);
    }

    // epilogue: store fp16 h1 + fused per-head logits
    int r0 = lane >> 2, c0l = 2 * (lane & 3);
    float asv[8][2], adv[8][2];
#pragma unroll
    for (int nt = 0; nt < 8; nt++) {
        int col = nw + nt * 8 + c0l;
        asv[nt][0] = __ldg(&as[col]);
        asv[nt][1] = __ldg(&as[col + 1]);
        adv[nt][0] = __ldg(&ad[col]);
        adv[nt][1] = __ldg(&ad[col + 1]);
    }
#pragma unroll
    for (int mt = 0; mt < 2; mt++) {
#pragma unroll
        for (int nt = 0; nt < 8; nt++) {
            int row = base + mw + mt * 16 + r0;
            int col = nw + nt * 8 + c0l;
            if (row < n)
                ((__half2*)g_h1)[(row * 128 + col) >> 1] =
                    __floats2half2_rn(acc[mt][nt][0], acc[mt][nt][1]);
            if (row + 8 < n)
                ((__half2*)g_h1)[((row + 8) * 128 + col) >> 1] =
                    __floats2half2_rn(acc[mt][nt][2], acc[mt][nt][3]);
        }
#pragma unroll
        for (int hl = 0; hl < 4; hl++) {
            int t0 = 2 * hl, t1 = 2 * hl + 1;
            float ps0 = acc[mt][t0][0] * asv[t0][0] + acc[mt][t0][1] * asv[t0][1]
                      + acc[mt][t1][0] * asv[t1][0] + acc[mt][t1][1] * asv[t1][1];
            float ps1 = acc[mt][t0][2] * asv[t0][0] + acc[mt][t0][3] * asv[t0][1]
                      + acc[mt][t1][2] * asv[t1][0] + acc[mt][t1][3] * asv[t1][1];
            float pd0 = acc[mt][t0][0] * adv[t0][0] + acc[mt][t0][1] * adv[t0][1]
                      + acc[mt][t1][0] * adv[t1][0] + acc[mt][t1][1] * adv[t1][1];
            float pd1 = acc[mt][t0][2] * adv[t0][0] + acc[mt][t0][3] * adv[t0][1]
                      + acc[mt][t1][2] * adv[t1][0] + acc[mt][t1][3] * adv[t1][1];
            ps0 += __shfl_xor_sync(0xffffffffu, ps0, 1);
            ps0 += __shfl_xor_sync(0xffffffffu, ps0, 2);
            ps1 += __shfl_xor_sync(0xffffffffu, ps1, 1);
            ps1 += __shfl_xor_sync(0xffffffffu, ps1, 2);
            pd0 += __shfl_xor_sync(0xffffffffu, pd0, 1);
            pd0 += __shfl_xor_sync(0xffffffffu, pd0, 2);
            pd1 += __shfl_xor_sync(0xffffffffu, pd1, 1);
            pd1 += __shfl_xor_sync(0xffffffffu, pd1, 2);
            if ((lane & 3) == 0) {
                int head = (nw >> 4) + hl;
                int row = base + mw + mt * 16 + r0;
                if (row < n) {
                    g_als1[row * 8 + head] = ps0;
                    g_ald1[row * 8 + head] = pd0;
                }
                if (row + 8 < n) {
                    g_als1[(row + 8) * 8 + head] = ps1;
                    g_ald1[(row + 8) * 8 + head] = pd1;
                }
            }
        }
    }
}

// ---------------- fused edge1 + GEMM2 + logits2 ------------------------------
__device__ __forceinline__ void e1acc(uint2 v, float ex, float4& acc, float& den) {
    float2 fa = __half22float2(*(__half2*)&v.x);
    float2 fb = __half22float2(*(__half2*)&v.y);
    acc.x = fmaf(ex, fa.x, acc.x);
    acc.y = fmaf(ex, fa.y, acc.y);
    acc.z = fmaf(ex, fb.x, acc.z);
    acc.w = fmaf(ex, fb.y, acc.w);
    den += ex;
}
__device__ __forceinline__ float lrelu_exp(float t) {
    t = t > 0.f ? t : 0.2f * t;
    return __expf(t);
}

// warp per dst node. After softmax-aggregate, the same warp does the
// [1x128]x[128x16] layer-2 projection from smem + layer-2 logits.
__global__ void __launch_bounds__(256) k_edge1g2(
        const float* __restrict__ b1, const float* __restrict__ W2,
        const float* __restrict__ as2v, const float* __restrict__ ad2v, int n) {
    __shared__ float Wsm[2048];       // W2 [128,16]
    __shared__ float hsm[8][128];     // per-warp hl2 row
    __shared__ float bsm[128];
    __shared__ float a2sm[16], d2sm[16];
    int tid = threadIdx.x;
    for (int i = tid; i < 2048; i += 256) Wsm[i] = W2[i];
    if (tid < 128) bsm[tid] = b1[tid];
    if (tid < 16) { a2sm[tid] = as2v[tid]; d2sm[tid] = ad2v[tid]; }
    __syncthreads();

    int warp = tid >> 5, lane = tid & 31;
    int head = lane >> 2;
    const uint2* h1v = (const uint2*)g_h1;
    int col = lane & 15;
    int kbase = (lane >> 4) * 64;
    float a2c = a2sm[col], d2c = d2sm[col];
    float b0 = bsm[4 * lane], b1v = bsm[4 * lane + 1],
          b2v = bsm[4 * lane + 2], b3v = bsm[4 * lane + 3];

    for (int d = blockIdx.x * 8 + warp; d < n; d += gridDim.x * 8) {
        float ald = g_ald1[d * 8 + head];
        int e = g_off[d];
        int end = e + g_deg[d] + 1;
        float4 acc = make_float4(0.f, 0.f, 0.f, 0.f);
        float den = 0.f;
        for (; e + 8 <= end; e += 8) {
            int s[8];
            float t[8];
            uint2 v[8];
#pragma unroll
            for (int j = 0; j < 8; j++) s[j] = __ldg(&g_csr[e + j]);
#pragma unroll
            for (int j = 0; j < 8; j++) t[j] = __ldg(&g_als1[s[j] * 8 + head]) + ald;
#pragma unroll
            for (int j = 0; j < 8; j++) v[j] = __ldg(&h1v[s[j] * 32 + lane]);
#pragma unroll
            for (int j = 0; j < 8; j++) e1acc(v[j], lrelu_exp(t[j]), acc, den);
        }
        for (; e + 4 <= end; e += 4) {
            int s0 = __ldg(&g_csr[e]);
            int s1 = __ldg(&g_csr[e + 1]);
            int s2 = __ldg(&g_csr[e + 2]);
            int s3 = __ldg(&g_csr[e + 3]);
            float t0 = __ldg(&g_als1[s0 * 8 + head]) + ald;
            float t1 = __ldg(&g_als1[s1 * 8 + head]) + ald;
            float t2 = __ldg(&g_als1[s2 * 8 + head]) + ald;
            float t3 = __ldg(&g_als1[s3 * 8 + head]) + ald;
            uint2 v0 = __ldg(&h1v[s0 * 32 + lane]);
            uint2 v1 = __ldg(&h1v[s1 * 32 + lane]);
            uint2 v2 = __ldg(&h1v[s2 * 32 + lane]);
            uint2 v3 = __ldg(&h1v[s3 * 32 + lane]);
            e1acc(v0, lrelu_exp(t0), acc, den);
            e1acc(v1, lrelu_exp(t1), acc, den);
            e1acc(v2, lrelu_exp(t2), acc, den);
            e1acc(v3, lrelu_exp(t3), acc, den);
        }
        for (; e < end; e++) {
            int s = __ldg(&g_csr[e]);
            float t = __ldg(&g_als1[s * 8 + head]) + ald;
            uint2 v = __ldg(&h1v[s * 32 + lane]);
            e1acc(v, lrelu_exp(t), acc, den);
        }
        float inv = 1.f / den;
        // hl2 row (relu) into this warp's smem slice
        hsm[warp][4 * lane + 0] = fmaxf(acc.x * inv + b0, 0.f);
        hsm[warp][4 * lane + 1] = fmaxf(acc.y * inv + b1v, 0.f);
        hsm[warp][4 * lane + 2] = fmaxf(acc.z * inv + b2v, 0.f);
        hsm[warp][4 * lane + 3] = fmaxf(acc.w * inv + b3v, 0.f);
        __syncwarp();
        // layer2 projection: lanes 0-15 k=0..63, lanes 16-31 k=64..127
        float part = 0.f;
        const float* hp = hsm[warp] + kbase;
        const float* wp = Wsm + kbase * 16 + col;
#pragma unroll 16
        for (int k = 0; k < 64; k++) part = fmaf(hp[k], wp[k * 16], part);
        part += __shfl_down_sync(0xffffffffu, part, 16);
        // lanes 0-15 now hold h2[d, col]
        float ps = part * a2c, pd = part * d2c;
        ps += __shfl_xor_sync(0xffffffffu, ps, 1);
        ps += __shfl_xor_sync(0xffffffffu, ps, 2);
        ps += __shfl_xor_sync(0xffffffffu, ps, 4);
        ps += __shfl_xor_sync(0xffffffffu, ps, 8);
        pd += __shfl_xor_sync(0xffffffffu, pd, 1);
        pd += __shfl_xor_sync(0xffffffffu, pd, 2);
        pd += __shfl_xor_sync(0xffffffffu, pd, 4);
        pd += __shfl_xor_sync(0xffffffffu, pd, 8);
        if (lane < 16) g_h2[d * 16 + col] = __float2half_rn(part);
        if (lane == 0) { g_als2[d] = ps; g_ald2[d] = pd; }
        __syncwarp();
    }
}

// ---------------- edge pass layer2: 16 lanes per dst node, 8-deep ------------
__global__ void k_edge2(const float* __restrict__ b2, float* __restrict__ out, int n) {
    int gid = blockIdx.x * blockDim.x + threadIdx.x;
    int node = gid >> 4, lane = gid & 15;
    if (node >= n) return;
    float ald = g_ald2[node];
    int e = g_off[node];
    int end = e + g_deg[node] + 1;
    float acc = 0.f, den = 0.f;
    for (; e + 8 <= end; e += 8) {
        int s[8];
        float t[8], h[8];
#pragma unroll
        for (int j = 0; j < 8; j++) s[j] = __ldg(&g_csr[e + j]);
#pragma unroll
        for (int j = 0; j < 8; j++) t[j] = __ldg(&g_als2[s[j]]) + ald;
#pragma unroll
        for (int j = 0; j < 8; j++) h[j] = __half2float(g_h2[s[j] * 16 + lane]);
#pragma unroll
        for (int j = 0; j < 8; j++) {
            float ex = lrelu_exp(t[j]);
            acc = fmaf(ex, h[j], acc);
            den += ex;
        }
    }
    for (; e < end; e++) {
        int s = __ldg(&g_csr[e]);
        float t = __ldg(&g_als2[s]) + ald;
        float ex = lrelu_exp(t);
        acc = fmaf(ex, __half2float(g_h2[s * 16 + lane]), acc);
        den += ex;
    }
    out[node * 16 + lane] = fmaxf(acc / den + b2[lane], 0.f);
}

// ---------------- launch -----------------------------------------------------
extern "C" void kernel_launch(void* const* d_in, const int* in_sizes, int n_in,
                              void* d_out, int out_size) {
    const float* x     = (const float*)d_in[0];
    const int*   ei    = (const int*)d_in[1];
    const float* W1    = (const float*)d_in[2];
    const float* asrc1 = (const float*)d_in[3];
    const float* adst1 = (const float*)d_in[4];
    const float* b1    = (const float*)d_in[5];
    const float* W2    = (const float*)d_in[6];
    const float* asrc2 = (const float*)d_in[7];
    const float* adst2 = (const float*)d_in[8];
    const float* b2    = (const float*)d_in[9];

    int n = in_sizes[0] / 128;
    int E = in_sizes[1] / 2;
    const int* src = ei;
    const int* dst = ei + E;
    int nb = (n + 255) / 256;

    // fork a side stream: CSR build runs concurrently with GEMM1
    cudaStream_t s2;
    cudaStreamCreateWithFlags(&s2, cudaStreamNonBlocking);
    cudaEvent_t evFork, evJoin;
    cudaEventCreateWithFlags(&evFork, cudaEventDisableTiming);
    cudaEventCreateWithFlags(&evJoin, cudaEventDisableTiming);

    cudaEventRecord(evFork, 0);
    cudaStreamWaitEvent(s2, evFork, 0);

    // CSR build chain on s2
    void* degp = nullptr;
    void* ctrp = nullptr;
    cudaGetSymbolAddress(&degp, g_deg);
    cudaGetSymbolAddress(&ctrp, g_ctr);
    cudaMemsetAsync(degp, 0, NMAX * sizeof(int), s2);
    cudaMemsetAsync(ctrp, 0, sizeof(int), s2);
    k_count<<<(E + 255) / 256, 256, 0, s2>>>(dst, E);
    k_alloc<<<nb, 256, 0, s2>>>(n);
    k_scatter<<<(E + 255) / 256, 256, 0, s2>>>(src, dst, E);
    cudaEventRecord(evJoin, s2);

    // GEMM1 (with fused logits) on the main stream, concurrent with CSR build
    const int SMEM1 = 2 * 128 * PAD * (int)sizeof(__half);  // 69632 -> 3 blocks/SM
    cudaFuncSetAttribute(k_gemm1, cudaFuncAttributeMaxDynamicSharedMemorySize, SMEM1);
    k_gemm1<<<(n + 127) / 128, 256, SMEM1>>>(x, W1, asrc1, adst1, n);

    // join: fused edge1+gemm2 needs both CSR and gemm1
    cudaStreamWaitEvent((cudaStream_t)0, evJoin, 0);
    k_edge1g2<<<(n + 7) / 8, 256>>>(b1, W2, asrc2, adst2, n);

    // layer 2 attention
    k_edge2<<<(n * 16 + 255) / 256, 256>>>(b2, (float*)d_out, n);

    cudaEventDestroy(evFork);
    cudaEventDestroy(evJoin);
    cudaStreamDestroy(s2);
}

// round 12
// speedup vs baseline: 1.2455x; 1.0130x over previous
#include <cstdint>
#include <cuda_runtime.h>
#include <cuda_fp16.h>

#define NMAX 50000
#define EMAX 800000
#define PAD 136   // fp16 row pitch for smem tiles (conflict-free ldmatrix)

// ---------------- device scratch --------------------------------------------
__device__ __half g_h1[NMAX * 128];
__device__ float  g_als1[NMAX * 8];
__device__ float  g_ald1[NMAX * 8];
__device__ __half g_h2[NMAX * 16];
__device__ float  g_als2[NMAX];
__device__ float  g_ald2[NMAX];
__device__ int    g_deg[NMAX];       // in-edge count (self loop added at alloc)
__device__ int    g_off[NMAX];       // start of each node's csr segment
__device__ int    g_rank[EMAX];
__device__ int    g_csr[EMAX + NMAX];
__device__ int    g_ctr;             // bump allocator for csr segments

// ---------------- CSR build --------------------------------------------------
__global__ void k_count(const int* __restrict__ dst, int E) {
    int i = blockIdx.x * blockDim.x + threadIdx.x;
    if (i < E) g_rank[i] = atomicAdd(&g_deg[dst[i]], 1);  // rank within dst segment
}

// segment allocation: block-local scan + ONE atomicAdd per block on a global
// counter (segment order across blocks is irrelevant — aggregation commutes).
__global__ void k_alloc(int n) {
    __shared__ int sm[256];
    __shared__ int sbase;
    int t = threadIdx.x;
    int i = blockIdx.x * 256 + t;
    int d = (i < n) ? (g_deg[i] + 1) : 0;  // +1 self loop
    sm[t] = d;
    __syncthreads();
    for (int o = 1; o < 256; o <<= 1) {
        int u = (t >= o) ? sm[t - o] : 0;
        __syncthreads();
        sm[t] += u;
        __syncthreads();
    }
    if (t == 255) sbase = atomicAdd(&g_ctr, sm[255]);
    __syncthreads();
    if (i < n) {
        int off = sbase + sm[t] - d;
        g_off[i] = off;
        g_csr[off] = i;  // self loop in slot 0
    }
}

__global__ void k_scatter(const int* __restrict__ src, const int* __restrict__ dst,
                          int E) {
    int i = blockIdx.x * blockDim.x + threadIdx.x;
    if (i < E) {
        int d = dst[i];
        g_csr[g_off[d] + 1 + g_rank[i]] = src[i];  // slot 0 is the self loop
    }
}

// ---------------- GEMM1 via tensor cores (plain fp16, fp32 acc) --------------
__device__ __forceinline__ void ldsm4(unsigned a, unsigned* r) {
    asm volatile("ldmatrix.sync.aligned.m8n8.x4.shared.b16 {%0,%1,%2,%3}, [%4];"
                 : "=r"(r[0]), "=r"(r[1]), "=r"(r[2]), "=r"(r[3]) : "r"(a));
}
__device__ __forceinline__ void ldsm4t(unsigned a, unsigned* r) {
    asm volatile("ldmatrix.sync.aligned.m8n8.x4.trans.shared.b16 {%0,%1,%2,%3}, [%4];"
                 : "=r"(r[0]), "=r"(r[1]), "=r"(r[2]), "=r"(r[3]) : "r"(a));
}
__device__ __forceinline__ void mma16816(float* c, const unsigned* a, unsigned b0, unsigned b1) {
    asm volatile("mma.sync.aligned.m16n8k16.row.col.f32.f16.f16.f32 "
                 "{%0,%1,%2,%3},{%4,%5,%6,%7},{%8,%9},{%0,%1,%2,%3};"
                 : "+f"(c[0]), "+f"(c[1]), "+f"(c[2]), "+f"(c[3])
                 : "r"(a[0]), "r"(a[1]), "r"(a[2]), "r"(a[3]), "r"(b0), "r"(b1));
}

// block: 256 threads (8 warps: 4 along M x 2 along N), C tile 64x128, K=128.
// 52 KB smem + ~85 regs -> 3 blocks/SM (occupancy was the binding resource).
// Epilogue also emits per-head attention logits.
__global__ void __launch_bounds__(256) k_gemm1(const float* __restrict__ x,
                                               const float* __restrict__ W,
                                               const float* __restrict__ as,
                                               const float* __restrict__ ad, int n) {
    extern __shared__ __half sh[];
    __half* Ah = sh;                 // 64 x PAD
    __half* Bh = Ah + 64 * PAD;      // 128 x PAD
    int tid = threadIdx.x;
    int base = blockIdx.x * 64;

    const float4* xg = (const float4*)x;
    for (int i = tid; i < 2048; i += 256) {
        int r = i >> 5, c4 = i & 31;
        int gr = base + r;
        float4 v = (gr < n) ? xg[gr * 32 + c4] : make_float4(0.f, 0.f, 0.f, 0.f);
        int cc = c4 * 4;
        *(__half2*)&Ah[r * PAD + cc] = __floats2half2_rn(v.x, v.y);
        *(__half2*)&Ah[r * PAD + cc + 2] = __floats2half2_rn(v.z, v.w);
    }
    const float4* wg = (const float4*)W;
    for (int i = tid; i < 4096; i += 256) {
        int r = i >> 5, c4 = i & 31;
        float4 v = wg[i];
        int cc = c4 * 4;
        *(__half2*)&Bh[r * PAD + cc] = __floats2half2_rn(v.x, v.y);
        *(__half2*)&Bh[r * PAD + cc + 2] = __floats2half2_rn(v.z, v.w);
    }
    __syncthreads();

    int warp = tid >> 5, lane = tid & 31;
    int mw = (warp >> 1) * 16;   // 4 warps along M, 16 rows each
    int nw = (warp & 1) * 64;    // 2 warps along N (= heads 0-3 / 4-7)
    int lr = lane & 15;
    int lk8 = (lane >> 4) * 8;

    float acc[8][4];
#pragma unroll
    for (int nt = 0; nt < 8; nt++)
#pragma unroll
        for (int j = 0; j < 4; j++) acc[nt][j] = 0.f;

#pragma unroll
    for (int kk = 0; kk < 8; kk++) {
        int k0 = kk * 16;
        unsigned ah[4];
        unsigned a = (unsigned)__cvta_generic_to_shared(
            &Ah[(mw + lr) * PAD + k0 + lk8]);
        ldsm4(a, ah);
        unsigned bh[8][2];
#pragma unroll
        for (int nt2 = 0; nt2 < 4; nt2++) {
            int n0 = nw + nt2 * 16;
            unsigned r4[4];
            a = (unsigned)__cvta_generic_to_shared(
                &Bh[(k0 + lr) * PAD + n0 + lk8]);
            ldsm4t(a, r4);
            bh[nt2 * 2][0] = r4[0]; bh[nt2 * 2][1] = r4[1];
            bh[nt2 * 2 + 1][0] = r4[2]; bh[nt2 * 2 + 1][1] = r4[3];
        }
#pragma unroll
        for (int nt = 0; nt < 8; nt++)
            mma16816(acc[nt], ah, bh[nt][0], bh[nt][1]);
    }

    // epilogue: store fp16 h1 + fused per-head logits
    int r0 = lane >> 2, c0l = 2 * (lane & 3);
#pragma unroll
    for (int nt = 0; nt < 8; nt++) {
        int row = base + mw + r0;
        int col = nw + nt * 8 + c0l;
        if (row < n)
            ((__half2*)g_h1)[(row * 128 + col) >> 1] =
                __floats2half2_rn(acc[nt][0], acc[nt][1]);
        if (row + 8 < n)
            ((__half2*)g_h1)[((row + 8) * 128 + col) >> 1] =
                __floats2half2_rn(acc[nt][2], acc[nt][3]);
    }
#pragma unroll
    for (int hl = 0; hl < 4; hl++) {
        int t0 = 2 * hl, t1 = 2 * hl + 1;
        int c0 = nw + t0 * 8 + c0l;
        int c1 = nw + t1 * 8 + c0l;
        float a00 = __ldg(&as[c0]), a01 = __ldg(&as[c0 + 1]);
        float a10 = __ldg(&as[c1]), a11 = __ldg(&as[c1 + 1]);
        float d00 = __ldg(&ad[c0]), d01 = __ldg(&ad[c0 + 1]);
        float d10 = __ldg(&ad[c1]), d11 = __ldg(&ad[c1 + 1]);
        float ps0 = acc[t0][0] * a00 + acc[t0][1] * a01
                  + acc[t1][0] * a10 + acc[t1][1] * a11;
        float ps1 = acc[t0][2] * a00 + acc[t0][3] * a01
                  + acc[t1][2] * a10 + acc[t1][3] * a11;
        float pd0 = acc[t0][0] * d00 + acc[t0][1] * d01
                  + acc[t1][0] * d10 + acc[t1][1] * d11;
        float pd1 = acc[t0][2] * d00 + acc[t0][3] * d01
                  + acc[t1][2] * d10 + acc[t1][3] * d11;
        ps0 += __shfl_xor_sync(0xffffffffu, ps0, 1);
        ps0 += __shfl_xor_sync(0xffffffffu, ps0, 2);
        ps1 += __shfl_xor_sync(0xffffffffu, ps1, 1);
        ps1 += __shfl_xor_sync(0xffffffffu, ps1, 2);
        pd0 += __shfl_xor_sync(0xffffffffu, pd0, 1);
        pd0 += __shfl_xor_sync(0xffffffffu, pd0, 2);
        pd1 += __shfl_xor_sync(0xffffffffu, pd1, 1);
        pd1 += __shfl_xor_sync(0xffffffffu, pd1, 2);
        if ((lane & 3) == 0) {
            int head = (nw >> 4) + hl;
            int row = base + mw + r0;
            if (row < n) {
                g_als1[row * 8 + head] = ps0;
                g_ald1[row * 8 + head] = pd0;
            }
            if (row + 8 < n) {
                g_als1[(row + 8) * 8 + head] = ps1;
                g_ald1[(row + 8) * 8 + head] = pd1;
            }
        }
    }
}

// ---------------- fused edge1 + GEMM2 + logits2 ------------------------------
__device__ __forceinline__ void e1acc(uint2 v, float ex, float4& acc, float& den) {
    float2 fa = __half22float2(*(__half2*)&v.x);
    float2 fb = __half22float2(*(__half2*)&v.y);
    acc.x = fmaf(ex, fa.x, acc.x);
    acc.y = fmaf(ex, fa.y, acc.y);
    acc.z = fmaf(ex, fb.x, acc.z);
    acc.w = fmaf(ex, fb.y, acc.w);
    den += ex;
}
__device__ __forceinline__ float lrelu_exp(float t) {
    t = t > 0.f ? t : 0.2f * t;
    return __expf(t);
}

// warp per dst node. After softmax-aggregate, the same warp does the
// [1x128]x[128x16] layer-2 projection from smem + layer-2 logits.
__global__ void __launch_bounds__(256) k_edge1g2(
        const float* __restrict__ b1, const float* __restrict__ W2,
        const float* __restrict__ as2v, const float* __restrict__ ad2v, int n) {
    __shared__ float Wsm[2048];       // W2 [128,16]
    __shared__ float hsm[8][128];     // per-warp hl2 row
    __shared__ float bsm[128];
    __shared__ float a2sm[16], d2sm[16];
    int tid = threadIdx.x;
    for (int i = tid; i < 2048; i += 256) Wsm[i] = W2[i];
    if (tid < 128) bsm[tid] = b1[tid];
    if (tid < 16) { a2sm[tid] = as2v[tid]; d2sm[tid] = ad2v[tid]; }
    __syncthreads();

    int warp = tid >> 5, lane = tid & 31;
    int head = lane >> 2;
    const uint2* h1v = (const uint2*)g_h1;
    int col = lane & 15;
    int kbase = (lane >> 4) * 64;
    float a2c = a2sm[col], d2c = d2sm[col];
    float b0 = bsm[4 * lane], b1v = bsm[4 * lane + 1],
          b2v = bsm[4 * lane + 2], b3v = bsm[4 * lane + 3];

    for (int d = blockIdx.x * 8 + warp; d < n; d += gridDim.x * 8) {
        float ald = g_ald1[d * 8 + head];
        int e = g_off[d];
        int end = e + g_deg[d] + 1;
        float4 acc = make_float4(0.f, 0.f, 0.f, 0.f);
        float den = 0.f;
        for (; e + 8 <= end; e += 8) {
            int s[8];
            float t[8];
            uint2 v[8];
#pragma unroll
            for (int j = 0; j < 8; j++) s[j] = __ldg(&g_csr[e + j]);
#pragma unroll
            for (int j = 0; j < 8; j++) t[j] = __ldg(&g_als1[s[j] * 8 + head]) + ald;
#pragma unroll
            for (int j = 0; j < 8; j++) v[j] = __ldg(&h1v[s[j] * 32 + lane]);
#pragma unroll
            for (int j = 0; j < 8; j++) e1acc(v[j], lrelu_exp(t[j]), acc, den);
        }
        for (; e + 4 <= end; e += 4) {
            int s0 = __ldg(&g_csr[e]);
            int s1 = __ldg(&g_csr[e + 1]);
            int s2 = __ldg(&g_csr[e + 2]);
            int s3 = __ldg(&g_csr[e + 3]);
            float t0 = __ldg(&g_als1[s0 * 8 + head]) + ald;
            float t1 = __ldg(&g_als1[s1 * 8 + head]) + ald;
            float t2 = __ldg(&g_als1[s2 * 8 + head]) + ald;
            float t3 = __ldg(&g_als1[s3 * 8 + head]) + ald;
            uint2 v0 = __ldg(&h1v[s0 * 32 + lane]);
            uint2 v1 = __ldg(&h1v[s1 * 32 + lane]);
            uint2 v2 = __ldg(&h1v[s2 * 32 + lane]);
            uint2 v3 = __ldg(&h1v[s3 * 32 + lane]);
            e1acc(v0, lrelu_exp(t0), acc, den);
            e1acc(v1, lrelu_exp(t1), acc, den);
            e1acc(v2, lrelu_exp(t2), acc, den);
            e1acc(v3, lrelu_exp(t3), acc, den);
        }
        for (; e < end; e++) {
            int s = __ldg(&g_csr[e]);
            float t = __ldg(&g_als1[s * 8 + head]) + ald;
            uint2 v = __ldg(&h1v[s * 32 + lane]);
            e1acc(v, lrelu_exp(t), acc, den);
        }
        float inv = 1.f / den;
        // hl2 row (relu) into this warp's smem slice
        hsm[warp][4 * lane + 0] = fmaxf(acc.x * inv + b0, 0.f);
        hsm[warp][4 * lane + 1] = fmaxf(acc.y * inv + b1v, 0.f);
        hsm[warp][4 * lane + 2] = fmaxf(acc.z * inv + b2v, 0.f);
        hsm[warp][4 * lane + 3] = fmaxf(acc.w * inv + b3v, 0.f);
        __syncwarp();
        // layer2 projection: lanes 0-15 k=0..63, lanes 16-31 k=64..127
        float part = 0.f;
        const float* hp = hsm[warp] + kbase;
        const float* wp = Wsm + kbase * 16 + col;
#pragma unroll 16
        for (int k = 0; k < 64; k++) part = fmaf(hp[k], wp[k * 16], part);
        part += __shfl_down_sync(0xffffffffu, part, 16);
        // lanes 0-15 now hold h2[d, col]
        float ps = part * a2c, pd = part * d2c;
        ps += __shfl_xor_sync(0xffffffffu, ps, 1);
        ps += __shfl_xor_sync(0xffffffffu, ps, 2);
        ps += __shfl_xor_sync(0xffffffffu, ps, 4);
        ps += __shfl_xor_sync(0xffffffffu, ps, 8);
        pd += __shfl_xor_sync(0xffffffffu, pd, 1);
        pd += __shfl_xor_sync(0xffffffffu, pd, 2);
        pd += __shfl_xor_sync(0xffffffffu, pd, 4);
        pd += __shfl_xor_sync(0xffffffffu, pd, 8);
        if (lane < 16) g_h2[d * 16 + col] = __float2half_rn(part);
        if (lane == 0) { g_als2[d] = ps; g_ald2[d] = pd; }
        __syncwarp();
    }
}

// ---------------- edge pass layer2: 16 lanes per dst node, 8-deep ------------
__global__ void k_edge2(const float* __restrict__ b2, float* __restrict__ out, int n) {
    int gid = blockIdx.x * blockDim.x + threadIdx.x;
    int node = gid >> 4, lane = gid & 15;
    if (node >= n) return;
    float ald = g_ald2[node];
    int e = g_off[node];
    int end = e + g_deg[node] + 1;
    float acc = 0.f, den = 0.f;
    for (; e + 8 <= end; e += 8) {
        int s[8];
        float t[8], h[8];
#pragma unroll
        for (int j = 0; j < 8; j++) s[j] = __ldg(&g_csr[e + j]);
#pragma unroll
        for (int j = 0; j < 8; j++) t[j] = __ldg(&g_als2[s[j]]) + ald;
#pragma unroll
        for (int j = 0; j < 8; j++) h[j] = __half2float(g_h2[s[j] * 16 + lane]);
#pragma unroll
        for (int j = 0; j < 8; j++) {
            float ex = lrelu_exp(t[j]);
            acc = fmaf(ex, h[j], acc);
            den += ex;
        }
    }
    for (; e < end; e++) {
        int s = __ldg(&g_csr[e]);
        float t = __ldg(&g_als2[s]) + ald;
        float ex = lrelu_exp(t);
        acc = fmaf(ex, __half2float(g_h2[s * 16 + lane]), acc);
        den += ex;
    }
    out[node * 16 + lane] = fmaxf(acc / den + b2[lane], 0.f);
}

// ---------------- launch -----------------------------------------------------
extern "C" void kernel_launch(void* const* d_in, const int* in_sizes, int n_in,
                              void* d_out, int out_size) {
    const float* x     = (const float*)d_in[0];
    const int*   ei    = (const int*)d_in[1];
    const float* W1    = (const float*)d_in[2];
    const float* asrc1 = (const float*)d_in[3];
    const float* adst1 = (const float*)d_in[4];
    const float* b1    = (const float*)d_in[5];
    const float* W2    = (const float*)d_in[6];
    const float* asrc2 = (const float*)d_in[7];
    const float* adst2 = (const float*)d_in[8];
    const float* b2    = (const float*)d_in[9];

    int n = in_sizes[0] / 128;
    int E = in_sizes[1] / 2;
    const int* src = ei;
    const int* dst = ei + E;
    int nb = (n + 255) / 256;

    // fork a side stream: CSR build runs concurrently with GEMM1
    cudaStream_t s2;
    cudaStreamCreateWithFlags(&s2, cudaStreamNonBlocking);
    cudaEvent_t evFork, evJoin;
    cudaEventCreateWithFlags(&evFork, cudaEventDisableTiming);
    cudaEventCreateWithFlags(&evJoin, cudaEventDisableTiming);

    cudaEventRecord(evFork, 0);
    cudaStreamWaitEvent(s2, evFork, 0);

    // CSR build chain on s2
    void* degp = nullptr;
    void* ctrp = nullptr;
    cudaGetSymbolAddress(&degp, g_deg);
    cudaGetSymbolAddress(&ctrp, g_ctr);
    cudaMemsetAsync(degp, 0, NMAX * sizeof(int), s2);
    cudaMemsetAsync(ctrp, 0, sizeof(int), s2);
    k_count<<<(E + 255) / 256, 256, 0, s2>>>(dst, E);
    k_alloc<<<nb, 256, 0, s2>>>(n);
    k_scatter<<<(E + 255) / 256, 256, 0, s2>>>(src, dst, E);
    cudaEventRecord(evJoin, s2);

    // GEMM1 (with fused logits) on the main stream, concurrent with CSR build
    const int SMEM1 = (64 + 128) * PAD * (int)sizeof(__half);  // 52224 -> 3+ blocks/SM
    cudaFuncSetAttribute(k_gemm1, cudaFuncAttributeMaxDynamicSharedMemorySize, SMEM1);
    k_gemm1<<<(n + 63) / 64, 256, SMEM1>>>(x, W1, asrc1, adst1, n);

    // join: fused edge1+gemm2 needs both CSR and gemm1
    cudaStreamWaitEvent((cudaStream_t)0, evJoin, 0);
    k_edge1g2<<<(n + 7) / 8, 256>>>(b1, W2, asrc2, adst2, n);

    // layer 2 attention
    k_edge2<<<(n * 16 + 255) / 256, 256>>>(b2, (float*)d_out, n);

    cudaEventDestroy(evFork);
    cudaEventDestroy(evJoin);
    cudaStreamDestroy(s2);
}